// round 2
// baseline (speedup 1.0000x reference)
#include <cuda_runtime.h>
#include <math.h>

#define BATCH   4
#define NPS     294912      // per-sample elements = 2*384*384
#define NBINS   64
#define CAP     4096        // candidate capacity per sample
#define BPS     72          // blocks per sample (72*4096 = 294912)
#define CHUNK   4096        // elements per block
#define RANK0   280165u     // floor(0.95*(NPS-1)), 0-indexed
#define V1      0.945f      // candidate window (95th pctile of U[0,1) is ~0.95 +- 4e-4)
#define V2      0.955f

// Scratch: zero-initialized at module load; k_final re-zeros what the next
// replay needs (d_hist, d_candcnt, d_cntbelow). No allocations anywhere.
__device__ float    d_hist[BATCH][2][NBINS];   // [sample][pred/gt][bin]
__device__ unsigned d_cand[BATCH][CAP];
__device__ unsigned d_candcnt[BATCH];
__device__ unsigned d_cntbelow[BATCH];
__device__ float    d_maxval[BATCH];

// Monotone float<->uint key mapping (handles negatives/general data)
__device__ __forceinline__ unsigned fkey(float f){
  unsigned u = __float_as_uint(f);
  return (u & 0x80000000u) ? ~u : (u | 0x80000000u);
}
__device__ __forceinline__ float finv(unsigned k){
  return __uint_as_float((k & 0x80000000u) ? (k & 0x7fffffffu) : ~k);
}

// ---------------------------------------------------------------------------
// K1: per-sample count(x < V1) + collect candidates in [V1, V2]
// ---------------------------------------------------------------------------
__global__ __launch_bounds__(256) void k_collect(const float* __restrict__ gt){
  const int s    = blockIdx.x / BPS;
  const int cb   = blockIdx.x % BPS;
  const int t    = threadIdx.x;
  const int lane = t & 31;
  const float4* p = reinterpret_cast<const float4*>(gt + (size_t)s * NPS + (size_t)cb * CHUNK);

  unsigned below = 0;
  #pragma unroll
  for (int i = 0; i < 4; i++){
    float4 v = p[t + 256 * i];
    float xs[4] = {v.x, v.y, v.z, v.w};
    #pragma unroll
    for (int j = 0; j < 4; j++){
      float x = xs[j];
      below += (x < V1) ? 1u : 0u;
      bool cand = (x >= V1) && (x <= V2);
      unsigned ball = __ballot_sync(0xffffffffu, cand);
      if (ball){
        int ldr = __ffs(ball) - 1;
        unsigned base = 0;
        if (lane == ldr) base = atomicAdd(&d_candcnt[s], (unsigned)__popc(ball));
        base = __shfl_sync(0xffffffffu, base, ldr);
        if (cand){
          unsigned pos = base + (unsigned)__popc(ball & ((1u << lane) - 1u));
          if (pos < CAP) d_cand[s][pos] = fkey(x);
        }
      }
    }
  }
  #pragma unroll
  for (int o = 16; o; o >>= 1) below += __shfl_down_sync(0xffffffffu, below, o);
  __shared__ unsigned swr[8];
  if (lane == 0) swr[t >> 5] = below;
  __syncthreads();
  if (t == 0){
    unsigned b = 0;
    #pragma unroll
    for (int i = 0; i < 8; i++) b += swr[i];
    atomicAdd(&d_cntbelow[s], b);
  }
}

// ---------------------------------------------------------------------------
// K2: per-sample exact order statistics -> max_val
//  fast path: bitonic-sort the <=4096 candidates in shared memory
//  fallback : exact 32-step bisection over the full sample (arbitrary data)
// ---------------------------------------------------------------------------
__global__ __launch_bounds__(1024) void k_select(const float* __restrict__ gt){
  const int s = blockIdx.x;
  const int t = threadIdx.x;
  __shared__ unsigned sk[CAP];
  __shared__ unsigned cred;

  const unsigned m  = d_candcnt[s];
  const unsigned c1 = d_cntbelow[s];
  unsigned vlo_key = 0u, vhi_key = 0u;
  const bool fast = (m <= CAP) && (RANK0 >= c1) && (RANK0 + 1u < c1 + m);

  if (fast){
    for (int i = t; i < CAP; i += 1024) sk[i] = (i < (int)m) ? d_cand[s][i] : 0xFFFFFFFFu;
    __syncthreads();
    for (int k = 2; k <= CAP; k <<= 1){
      for (int j = k >> 1; j > 0; j >>= 1){
        for (int i = t; i < CAP; i += 1024){
          int ixj = i ^ j;
          if (ixj > i){
            unsigned a = sk[i], b = sk[ixj];
            bool up = ((i & k) == 0);
            if ((a > b) == up){ sk[i] = b; sk[ixj] = a; }
          }
        }
        __syncthreads();
      }
    }
    vlo_key = sk[RANK0 - c1];
    vhi_key = sk[RANK0 + 1u - c1];
  } else {
    const float* g = gt + (size_t)s * NPS;
    unsigned res[2];
    for (int q = 0; q < 2; q++){
      unsigned need = RANK0 + 1u + (unsigned)q;   // 1-indexed count target
      unsigned lo = 0u, hi = 0xFFFFFFFFu;
      while (lo < hi){
        unsigned mid = lo + ((hi - lo) >> 1);
        unsigned c = 0;
        for (int i = t; i < NPS; i += 1024) c += (fkey(g[i]) <= mid) ? 1u : 0u;
        #pragma unroll
        for (int o = 16; o; o >>= 1) c += __shfl_down_sync(0xffffffffu, c, o);
        if (t == 0) cred = 0u;
        __syncthreads();
        if ((t & 31) == 0) atomicAdd(&cred, c);
        __syncthreads();
        unsigned tot = cred;
        __syncthreads();
        if (tot >= need) hi = mid; else lo = mid + 1u;
      }
      res[q] = lo;
    }
    vlo_key = res[0];
    vhi_key = res[1];
  }

  if (t == 0){
    float vlo = finv(vlo_key), vhi = finv(vhi_key);
    float pos = 0.95f * (float)(NPS - 1);     // matches jax float32 index math
    float fr  = pos - floorf(pos);
    d_maxval[s] = vlo + fr * (vhi - vlo);
  }
}

// ---------------------------------------------------------------------------
// K3: triangular soft histogram (pred + gt), shared-atomic scatter
// ---------------------------------------------------------------------------
__device__ __forceinline__ void scat(float* h, float x, float inv){
  float tt = x * inv;
  if (tt <= -1.0f || tt >= (float)NBINS) return;   // no bin can receive weight
  float fj = floorf(tt);
  int   j  = (int)fj;
  float f  = tt - fj;
  if (j >= 0)          atomicAdd(&h[j],     1.0f - f);
  if (j + 1 < NBINS)   atomicAdd(&h[j + 1], f);
}

__global__ __launch_bounds__(256) void k_hist(const float* __restrict__ pred,
                                              const float* __restrict__ gt){
  const int s  = blockIdx.x / BPS;
  const int cb = blockIdx.x % BPS;
  const int t  = threadIdx.x;
  __shared__ float shp[NBINS], shg[NBINS];
  if (t < NBINS){ shp[t] = 0.0f; shg[t] = 0.0f; }
  __syncthreads();

  const float mv  = d_maxval[s];
  const float bw  = mv * (1.0f / NBINS);    // == edges[1]-edges[0] in the reference
  const float inv = 1.0f / bw;
  const size_t base = (size_t)s * NPS + (size_t)cb * CHUNK;
  const float4* pp = reinterpret_cast<const float4*>(pred + base);
  const float4* pg = reinterpret_cast<const float4*>(gt   + base);

  #pragma unroll
  for (int i = 0; i < 4; i++){
    float4 a = pp[t + 256 * i];
    float4 b = pg[t + 256 * i];
    scat(shp, a.x, inv); scat(shp, a.y, inv); scat(shp, a.z, inv); scat(shp, a.w, inv);
    scat(shg, b.x, inv); scat(shg, b.y, inv); scat(shg, b.z, inv); scat(shg, b.w, inv);
  }
  __syncthreads();
  if (t < NBINS){
    atomicAdd(&d_hist[s][0][t], shp[t]);
    atomicAdd(&d_hist[s][1][t], shg[t]);
  }
}

// ---------------------------------------------------------------------------
// K4: normalize, weight, L1-mean, batch-mean; then zero scratch for next replay
// ---------------------------------------------------------------------------
__global__ __launch_bounds__(256) void k_final(float* __restrict__ out){
  const int t = threadIdx.x, w = t >> 5, l = t & 31;
  __shared__ float ssum[BATCH][2];
  __shared__ float sloss[BATCH];

  // per-(sample,tensor) sums: 8 warps, one each
  {
    int s = w >> 1, ti = w & 1;
    float v = d_hist[s][ti][l] + d_hist[s][ti][l + 32];
    #pragma unroll
    for (int o = 16; o; o >>= 1) v += __shfl_down_sync(0xffffffffu, v, o);
    if (l == 0) ssum[s][ti] = v;
  }
  __syncthreads();

  if (w < BATCH){
    int s = w;
    float invP = 1.0f / ssum[s][0];
    float invG = 1.0f / ssum[s][1];
    float acc = 0.0f;
    for (int j = l; j < NBINS; j += 32){
      float wj = expf(0.4f * (float)j * (1.0f / (float)NBINS));
      float pv = d_hist[s][0][j] * invP * wj;
      float gv = d_hist[s][1][j] * invG * wj;
      acc += fabsf(pv - gv);
    }
    #pragma unroll
    for (int o = 16; o; o >>= 1) acc += __shfl_down_sync(0xffffffffu, acc, o);
    if (l == 0) sloss[s] = acc * (1.0f / (float)NBINS);
  }
  __syncthreads();

  if (t == 0) out[0] = (sloss[0] + sloss[1] + sloss[2] + sloss[3]) * 0.25f;
  __syncthreads();

  // re-zero scratch so the next graph replay starts clean (first call uses
  // static zero-init of __device__ globals)
  float* hz = (float*)d_hist;          // 512 floats
  hz[t] = 0.0f; hz[t + 256] = 0.0f;
  if (t < BATCH){ d_candcnt[t] = 0u; d_cntbelow[t] = 0u; }
}

// ---------------------------------------------------------------------------
extern "C" void kernel_launch(void* const* d_in, const int* in_sizes, int n_in,
                              void* d_out, int out_size){
  (void)in_sizes; (void)n_in; (void)out_size;
  const float* pred = (const float*)d_in[0];
  const float* gt   = (const float*)d_in[1];
  float* out        = (float*)d_out;

  k_collect<<<BATCH * BPS, 256>>>(gt);
  k_select <<<BATCH, 1024>>>(gt);
  k_hist   <<<BATCH * BPS, 256>>>(pred, gt);
  k_final  <<<1, 256>>>(out);
}

// round 4
// speedup vs baseline: 1.8486x; 1.8486x over previous
#include <cuda_runtime.h>
#include <math.h>

#define BATCH   4
#define NPS     294912      // per-sample elements = 2*384*384
#define NBINS   64
#define CAP     4096        // candidate capacity per sample
#define BPS1    72          // k1 blocks per sample (72*4096 = 294912)
#define CHUNK1  4096
#define BPS2    72          // k2 blocks per sample
#define CHUNK2  4096
#define GRID2   (BATCH * BPS2)
#define HT      128         // k2 threads (private-histogram owners)
#define PAD     129         // bank-conflict-free stride
#define RANK0   280165u     // floor(0.95*(NPS-1)), 0-indexed
#define V1      0.945f
#define V2      0.955f

// Scratch: zero-init at module load; tail blocks re-zero for the next replay.
__device__ float    d_hist[BATCH][2][NBINS];
__device__ unsigned d_cand[BATCH][CAP];
__device__ unsigned d_candcnt[BATCH];
__device__ unsigned d_cntbelow[BATCH];
__device__ float    d_maxval[BATCH];
__device__ unsigned d_done1[BATCH];
__device__ unsigned d_done2;

__device__ __forceinline__ unsigned fkey(float f){
  unsigned u = __float_as_uint(f);
  return (u & 0x80000000u) ? ~u : (u | 0x80000000u);
}
__device__ __forceinline__ float finv(unsigned k){
  return __uint_as_float((k & 0x80000000u) ? (k & 0x7fffffffu) : ~k);
}
__device__ __forceinline__ unsigned wred(unsigned v){
  #pragma unroll
  for (int o = 16; o; o >>= 1) v += __shfl_down_sync(0xffffffffu, v, o);
  return v;
}

// ---------------------------------------------------------------------------
// K1: collect candidates + count-below; last block per sample does exact
//     order-statistic selection (radix-select fast path, bisection fallback)
// ---------------------------------------------------------------------------
__global__ __launch_bounds__(256) void k_collect(const float* __restrict__ gt){
  const int s    = blockIdx.x / BPS1;
  const int cb   = blockIdx.x % BPS1;
  const int t    = threadIdx.x;
  const int lane = t & 31;
  const int w    = t >> 5;

  __shared__ unsigned sk[CAP];
  __shared__ unsigned cnt[256];
  __shared__ unsigned wsum[8];
  __shared__ unsigned wpre[8];
  __shared__ unsigned sb_bucket, sb_rank;
  __shared__ unsigned s_ticket;
  __shared__ unsigned swr[8];
  __shared__ unsigned cred;

  // ---- collect phase ----
  {
    const float4* p = reinterpret_cast<const float4*>(gt + (size_t)s * NPS + (size_t)cb * CHUNK1);
    unsigned below = 0;
    #pragma unroll
    for (int i = 0; i < 4; i++){
      float4 v = p[t + 256 * i];
      float xs[4] = {v.x, v.y, v.z, v.w};
      #pragma unroll
      for (int j = 0; j < 4; j++){
        float x = xs[j];
        below += (x < V1) ? 1u : 0u;
        bool cand = (x >= V1) && (x <= V2);
        unsigned ball = __ballot_sync(0xffffffffu, cand);
        if (ball){
          int ldr = __ffs(ball) - 1;
          unsigned base = 0;
          if (lane == ldr) base = atomicAdd(&d_candcnt[s], (unsigned)__popc(ball));
          base = __shfl_sync(0xffffffffu, base, ldr);
          if (cand){
            unsigned pos = base + (unsigned)__popc(ball & ((1u << lane) - 1u));
            if (pos < CAP) d_cand[s][pos] = fkey(x);
          }
        }
      }
    }
    below = wred(below);
    if (lane == 0) swr[w] = below;
    __syncthreads();
    if (t == 0){
      unsigned b = 0;
      #pragma unroll
      for (int i = 0; i < 8; i++) b += swr[i];
      atomicAdd(&d_cntbelow[s], b);
    }
  }

  // ---- ticket: last block of this sample does selection ----
  __threadfence();
  if (t == 0) s_ticket = atomicAdd(&d_done1[s], 1u);
  __syncthreads();
  if (s_ticket != BPS1 - 1) return;
  if (t == 0) d_done1[s] = 0;          // reset for next replay

  const unsigned m  = __ldcg(&d_candcnt[s]);
  const unsigned c1 = __ldcg(&d_cntbelow[s]);
  unsigned vlo_key = 0u, vhi_key = 0u;
  const bool fast = (m <= CAP) && (RANK0 >= c1) && (RANK0 + 1u < c1 + m);

  if (fast){
    for (int i = t; i < (int)m; i += 256) sk[i] = __ldcg(&d_cand[s][i]);
    __syncthreads();

    const unsigned rlo = RANK0 - c1;
    unsigned r = rlo;
    unsigned pref = 0u;                 // accumulated high bits (low-aligned)
    #pragma unroll
    for (int shift = 24; shift >= 0; shift -= 8){
      cnt[t] = 0u;
      __syncthreads();
      for (int i = t; i < (int)m; i += 256){
        unsigned k = sk[i];
        bool ok = (shift == 24) || ((k >> (shift + 8)) == pref);
        if (ok) atomicAdd(&cnt[(k >> shift) & 255u], 1u);
      }
      __syncthreads();
      // exclusive scan of 256 counts
      unsigned v = cnt[t], inc = v;
      #pragma unroll
      for (int o = 1; o < 32; o <<= 1){
        unsigned u = __shfl_up_sync(0xffffffffu, inc, o);
        if (lane >= o) inc += u;
      }
      if (lane == 31) wsum[w] = inc;
      __syncthreads();
      if (t < 8){
        unsigned a = wsum[t], ia = a;
        #pragma unroll
        for (int o = 1; o < 8; o <<= 1){
          unsigned u = __shfl_up_sync(0xffu, ia, o);
          if (t >= o) ia += u;
        }
        wpre[t] = ia - a;               // exclusive warp base
      }
      __syncthreads();
      unsigned excl = wpre[w] + inc - v;
      if (v > 0u && excl <= r && r < excl + v){
        sb_bucket = (unsigned)t;
        sb_rank   = r - excl;
      }
      __syncthreads();
      pref = (pref << 8) | sb_bucket;
      r    = sb_rank;
      __syncthreads();
    }
    vlo_key = pref;

    // adjacent order statistic: count(<= vlo) and min(> vlo)
    unsigned le = 0u, mg = 0xFFFFFFFFu;
    for (int i = t; i < (int)m; i += 256){
      unsigned k = sk[i];
      le += (k <= vlo_key) ? 1u : 0u;
      if (k > vlo_key) mg = min(mg, k);
    }
    le = wred(le);
    #pragma unroll
    for (int o = 16; o; o >>= 1) mg = min(mg, __shfl_down_sync(0xffffffffu, mg, o));
    if (lane == 0){ swr[w] = le; cnt[w] = mg; }
    __syncthreads();
    if (t == 0){
      unsigned let = 0u, mgt = 0xFFFFFFFFu;
      #pragma unroll
      for (int i = 0; i < 8; i++){ let += swr[i]; mgt = min(mgt, cnt[i]); }
      vhi_key = (let >= rlo + 2u) ? vlo_key : mgt;
      float vlo = finv(vlo_key), vhi = finv(vhi_key);
      float pos = 0.95f * (float)(NPS - 1);
      float fr  = pos - floorf(pos);
      d_maxval[s] = vlo + fr * (vhi - vlo);
    }
  } else {
    // exact bisection fallback (arbitrary data; never taken on this input)
    const float* g = gt + (size_t)s * NPS;
    unsigned res[2];
    for (int q = 0; q < 2; q++){
      unsigned need = RANK0 + 1u + (unsigned)q;
      unsigned lo = 0u, hi = 0xFFFFFFFFu;
      while (lo < hi){
        unsigned mid = lo + ((hi - lo) >> 1);
        unsigned c = 0u;
        for (int i = t; i < NPS; i += 256) c += (fkey(g[i]) <= mid) ? 1u : 0u;
        c = wred(c);
        if (t == 0) cred = 0u;
        __syncthreads();
        if (lane == 0) atomicAdd(&cred, c);
        __syncthreads();
        unsigned tot = cred;
        __syncthreads();
        if (tot >= need) hi = mid; else lo = mid + 1u;
      }
      res[q] = lo;
    }
    if (t == 0){
      float vlo = finv(res[0]), vhi = finv(res[1]);
      float pos = 0.95f * (float)(NPS - 1);
      float fr  = pos - floorf(pos);
      d_maxval[s] = vlo + fr * (vhi - vlo);
    }
  }
}

// ---------------------------------------------------------------------------
// K2: atomic-free per-thread privatized soft histogram + fused finalize
// ---------------------------------------------------------------------------
__global__ __launch_bounds__(HT) void k_hist(const float* __restrict__ pred,
                                             const float* __restrict__ gt,
                                             float* __restrict__ out){
  const int s  = blockIdx.x / BPS2;
  const int cb = blockIdx.x % BPS2;
  const int t  = threadIdx.x;
  const int lane = t & 31;
  const int w    = t >> 5;

  __shared__ float sh[NBINS * PAD];     // 33 KB, owner-column privatized
  __shared__ unsigned s_ticket;
  __shared__ float ssum[BATCH][2];
  __shared__ float sloss[BATCH];

  const float mv  = d_maxval[s];
  const float bw  = mv * (1.0f / NBINS);
  const float inv = 1.0f / bw;
  const size_t base = (size_t)s * NPS + (size_t)cb * CHUNK2;

  #pragma unroll
  for (int ph = 0; ph < 2; ph++){
    const float* src = (ph == 0) ? pred : gt;
    const float4* p4 = reinterpret_cast<const float4*>(src + base);

    // zero private columns
    #pragma unroll
    for (int i = t; i < NBINS * PAD; i += HT) sh[i] = 0.0f;
    __syncthreads();

    #pragma unroll
    for (int i = 0; i < CHUNK2 / 4 / HT; i++){      // 8 float4 per thread
      float4 v = p4[t + HT * i];
      float xs[4] = {v.x, v.y, v.z, v.w};
      #pragma unroll
      for (int j = 0; j < 4; j++){
        float tt = xs[j] * inv;
        if (tt <= -1.0f || tt >= (float)NBINS) continue;
        float fj = floorf(tt);
        int   b  = (int)fj;
        float f  = tt - fj;
        if (b >= 0)         sh[b * PAD + t]       += 1.0f - f;   // conflict-free RMW
        if (b + 1 < NBINS)  sh[(b + 1) * PAD + t] += f;
      }
    }
    __syncthreads();

    // reduce 128 owner columns per bin, flush to global
    if (t < NBINS){
      float a = 0.0f;
      #pragma unroll 8
      for (int p = 0; p < HT; p++) a += sh[t * PAD + p];
      atomicAdd(&d_hist[s][ph][t], a);
    }
    __syncthreads();
  }

  // ---- ticket: globally-last block finalizes ----
  __threadfence();
  if (t == 0) s_ticket = atomicAdd(&d_done2, 1u);
  __syncthreads();
  if (s_ticket != GRID2 - 1) return;
  if (t == 0) d_done2 = 0u;

  // per-(sample,tensor) normalizer sums: warp w -> sample w, both tensors
  #pragma unroll
  for (int ti = 0; ti < 2; ti++){
    float v = __ldcg(&d_hist[w][ti][lane]) + __ldcg(&d_hist[w][ti][lane + 32]);
    #pragma unroll
    for (int o = 16; o; o >>= 1) v += __shfl_down_sync(0xffffffffu, v, o);
    if (lane == 0) ssum[w][ti] = v;
  }
  __syncthreads();

  {
    float invP = 1.0f / ssum[w][0];
    float invG = 1.0f / ssum[w][1];
    float acc = 0.0f;
    #pragma unroll
    for (int j = lane; j < NBINS; j += 32){
      float wj = expf(0.4f * (float)j * (1.0f / (float)NBINS));
      float pv = __ldcg(&d_hist[w][0][j]) * invP * wj;
      float gv = __ldcg(&d_hist[w][1][j]) * invG * wj;
      acc += fabsf(pv - gv);
    }
    #pragma unroll
    for (int o = 16; o; o >>= 1) acc += __shfl_down_sync(0xffffffffu, acc, o);
    if (lane == 0) sloss[w] = acc * (1.0f / (float)NBINS);
  }
  __syncthreads();

  if (t == 0) out[0] = (sloss[0] + sloss[1] + sloss[2] + sloss[3]) * 0.25f;
  __syncthreads();

  // re-zero scratch for next graph replay
  {
    float* hz = (float*)d_hist;         // 512 floats
    #pragma unroll
    for (int i = t; i < 512; i += HT) hz[i] = 0.0f;
    if (t < BATCH){ d_candcnt[t] = 0u; d_cntbelow[t] = 0u; }
  }
}

// ---------------------------------------------------------------------------
extern "C" void kernel_launch(void* const* d_in, const int* in_sizes, int n_in,
                              void* d_out, int out_size){
  (void)in_sizes; (void)n_in; (void)out_size;
  const float* pred = (const float*)d_in[0];
  const float* gt   = (const float*)d_in[1];
  float* out        = (float*)d_out;

  k_collect<<<BATCH * BPS1, 256>>>(gt);
  k_hist   <<<GRID2, HT>>>(pred, gt, out);
}